// round 9
// baseline (speedup 1.0000x reference)
#include <cuda_runtime.h>
#include <cuda_bf16.h>

#define BN 8192
#define EN 8
#define HN 128
#define TS 128
#define NT (BN / TS)                 // 64 tiles per dim
#define NPAIR (NT * (NT + 1) / 2)    // 2080 upper-triangular tile pairs
#define GRID_PAIR 296                // 2 CTAs/SM, one wave
#define PREP_BLKS (BN / 8)           // 1024

// dynamic smem layout (bytes)
#define SM_STAGE   16384             // 8KB A + 8KB B per stage
#define SM_STAGES  (3 * SM_STAGE)    // 49152
#define SM_LI      (SM_STAGES)       // L tile, i side  (4 KB)
#define SM_PAI     (SM_LI  + 4096)   // Pa tile, i side
#define SM_LJ      (SM_PAI + 4096)
#define SM_PAJ     (SM_LJ  + 4096)
#define SM_TOTAL   (SM_PAJ + 4096)   // 65536

// ---------------- device scratch -------------------------------------------
// bf16 main-GEMM tile images in 4 K-chunks of 32 (same layout as R8):
//   byte(r,q) = (r>>1)*128 + (((r&1)*4) | (q ^ ((r>>1)&3)))*16,  q in 0..3
__device__ __align__(1024) unsigned char g_ct[4][NT][TS * 64];  // 2 MB
// augmented KL operand tiles, bf16, 16 cols per row (32 B), layout off16():
//   L_i  = [logp_i(8), 1, 0 x7] ; Pa_i = [p_i(8), -a_i, 0 x7]
__device__ __align__(1024) unsigned char g_L16[NT][TS * 32];    // 256 KB
__device__ __align__(1024) unsigned char g_Pa16[NT][TS * 32];   // 256 KB
// prep per-block partials (written unconditionally -> no zeroing kernel)
__device__ double g_pp_task[PREP_BLKS], g_pp_eff[PREP_BLKS], g_pp_ent[PREP_BLKS];
__device__ float  g_pp_us[PREP_BLKS * EN];
// pair per-CTA partials + never-reset ticket (modular check is replay-safe)
__device__ double g_pair_kl[GRID_PAIR];
__device__ double g_pair_cnt[GRID_PAIR];
__device__ unsigned g_ticket;

// ---------------- PTX helpers ----------------------------------------------
__device__ __forceinline__ unsigned smem_u32(const void* p) {
    unsigned a;
    asm("{ .reg .u64 t; cvta.to.shared.u64 t, %1; cvt.u32.u64 %0, t; }"
        : "=r"(a) : "l"(p));
    return a;
}
__device__ __forceinline__ void ldsm4(unsigned* r, unsigned addr) {
    asm volatile("ldmatrix.sync.aligned.m8n8.x4.shared.b16 {%0,%1,%2,%3}, [%4];"
                 : "=r"(r[0]), "=r"(r[1]), "=r"(r[2]), "=r"(r[3]) : "r"(addr));
}
__device__ __forceinline__ void mma16816(float* d, const unsigned* a, const unsigned* b) {
    asm volatile(
        "mma.sync.aligned.m16n8k16.row.col.f32.bf16.bf16.f32 "
        "{%0,%1,%2,%3}, {%4,%5,%6,%7}, {%8,%9}, {%0,%1,%2,%3};"
        : "+f"(d[0]), "+f"(d[1]), "+f"(d[2]), "+f"(d[3])
        : "r"(a[0]), "r"(a[1]), "r"(a[2]), "r"(a[3]), "r"(b[0]), "r"(b[1]));
}
__device__ __forceinline__ void cpa16(unsigned dst, const void* src) {
    asm volatile("cp.async.cg.shared.global [%0], [%1], 16;"
                 :: "r"(dst), "l"(src) : "memory");
}
#define CP_COMMIT() asm volatile("cp.async.commit_group;" ::: "memory")
#define CP_WAIT1()  asm volatile("cp.async.wait_group 1;" ::: "memory")
#define CP_WAIT0()  asm volatile("cp.async.wait_group 0;" ::: "memory")

// swizzled byte offset within a main-GEMM K-chunk tile
__device__ __forceinline__ unsigned coff(int r, int q) {
    return ((unsigned)(r >> 1) << 7) +
           ((((unsigned)(r & 1) << 2) | ((unsigned)q ^ ((unsigned)(r >> 1) & 3))) << 4);
}
// byte offset within a 128x16 bf16 augmented tile (32 B/row, 4 rows/128B line,
// XOR on chunk bit keeps ldmatrix 8-row loads conflict-free)
__device__ __forceinline__ unsigned off16(int r, int q) {
    return ((unsigned)(r >> 2) << 7) +
           ((((unsigned)(r & 3) << 1) + ((unsigned)q ^ ((unsigned)(r >> 2) & 1))) << 4);
}
__device__ __forceinline__ unsigned pkbf(float a, float b) {
    return (unsigned)__bfloat16_as_ushort(__float2bfloat16_rn(a)) |
           ((unsigned)__bfloat16_as_ushort(__float2bfloat16_rn(b)) << 16);
}
__device__ __forceinline__ double wredd(double v) {
#pragma unroll
    for (int o = 16; o > 0; o >>= 1) v += __shfl_xor_sync(0xffffffffu, v, o);
    return v;
}

// ---------------- per-row preprocessing + cheap loss partials ---------------
__global__ __launch_bounds__(256) void prep_kernel(
    const float* __restrict__ logits,
    const int* __restrict__ targets,
    const float* __restrict__ rp,
    const float* __restrict__ emb) {
    int warp = threadIdx.x >> 5, lane = threadIdx.x & 31;
    int row = blockIdx.x * 8 + warp;
    __shared__ float  s_us[EN];
    __shared__ double s_task[8], s_eff[8], s_ent[8];
    if (threadIdx.x < EN) s_us[threadIdx.x] = 0.f;
    __syncthreads();

    // normalize embedding row (float4 per lane = 4 consecutive k-cols)
    float4 v = *(const float4*)(emb + (size_t)row * HN + lane * 4);
    float ss = v.x * v.x + v.y * v.y + v.z * v.z + v.w * v.w;
#pragma unroll
    for (int o = 16; o > 0; o >>= 1) ss += __shfl_xor_sync(0xffffffffu, ss, o);
    float inv = rsqrtf(ss);
    float4 w = make_float4(v.x * inv, v.y * inv, v.z * inv, v.w * inv);

    // store bf16 into chunked swizzled main-GEMM tile image
    {
        int cc = lane >> 3;                  // K-chunk 0..3
        int q  = (lane & 7) >> 1;            // 16B chunk in row
        int lr = row & (TS - 1);
        unsigned off = coff(lr, q) + (unsigned)(lane & 1) * 8;
        uint2 val = make_uint2(pkbf(w.x, w.y), pkbf(w.z, w.w));
        *(uint2*)(&g_ct[cc][row >> 7][off]) = val;
    }

    // routing-prob softmax over E=8
    float r = (lane < EN) ? rp[row * EN + lane] : -3.0e38f;
    float m = r;
#pragma unroll
    for (int o = 4; o > 0; o >>= 1) m = fmaxf(m, __shfl_xor_sync(0xffffffffu, m, o));
    float ex = (lane < EN) ? expf(r - m) : 0.f;
    float es = ex;
#pragma unroll
    for (int o = 4; o > 0; o >>= 1) es += __shfl_xor_sync(0xffffffffu, es, o);
    float lse = m + logf(es);
    float lp = r - lse;
    float p  = expf(lp);

    float av  = (lane < EN) ? p * lp : 0.f;
    float evv = (lane < EN && r < 0.1f) ? r : 0.f;
    float nv  = (lane < EN) ? r * logf(r + 1e-8f) : 0.f;
#pragma unroll
    for (int o = 4; o > 0; o >>= 1) {
        av  += __shfl_xor_sync(0xffffffffu, av, o);
        evv += __shfl_xor_sync(0xffffffffu, evv, o);
        nv  += __shfl_xor_sync(0xffffffffu, nv, o);
    }

    // build augmented bf16 tiles: L = [logp,1,0x7], Pa = [p,-a,0x7]
    {
        float l0 = __shfl_sync(0xffffffffu, lp, (lane & 3) * 2);
        float l1 = __shfl_sync(0xffffffffu, lp, (lane & 3) * 2 + 1);
        float p0 = __shfl_sync(0xffffffffu, p,  (lane & 3) * 2);
        float p1 = __shfl_sync(0xffffffffu, p,  (lane & 3) * 2 + 1);
        if (lane < 8) {
            unsigned Lw, Pw;
            if (lane < 4)      { Lw = pkbf(l0, l1);   Pw = pkbf(p0, p1); }
            else if (lane == 4){ Lw = pkbf(1.f, 0.f); Pw = pkbf(-av, 0.f); }
            else               { Lw = 0u;             Pw = 0u; }
            int lr = row & (TS - 1);
            unsigned off = off16(lr, lane >> 2) + (unsigned)(lane & 3) * 4;
            *(unsigned*)(&g_L16 [row >> 7][off]) = Lw;
            *(unsigned*)(&g_Pa16[row >> 7][off]) = Pw;
        }
    }

    if (lane < EN) atomicAdd(&s_us[lane], r);
    if (lane == 0) {
        float l0 = logits[row * 3 + 0], l1 = logits[row * 3 + 1], l2 = logits[row * 3 + 2];
        float mm = fmaxf(l0, fmaxf(l1, l2));
        float lsm = mm + logf(expf(l0 - mm) + expf(l1 - mm) + expf(l2 - mm));
        int t = targets[row];
        float lt = (t == 0) ? l0 : ((t == 1) ? l1 : l2);
        s_task[warp] = (double)(lsm - lt);
        s_eff[warp]  = (double)evv;
        s_ent[warp]  = (double)nv;
    }
    __syncthreads();
    if (threadIdx.x == 0) {
        double a = 0, b = 0, c = 0;
        for (int i = 0; i < 8; i++) { a += s_task[i]; b += s_eff[i]; c += s_ent[i]; }
        g_pp_task[blockIdx.x] = a;
        g_pp_eff[blockIdx.x]  = b;
        g_pp_ent[blockIdx.x]  = c;
    }
    if (threadIdx.x < EN) g_pp_us[blockIdx.x * EN + threadIdx.x] = s_us[threadIdx.x];
}

// ---------------- HMMA pair kernel: pipeline + tensor-core KL epilogue ------
// Mainloop identical to R8 (3-stage flat cp.async). Epilogue: pack sim masks
// into 2 regs (+popc for cnt), then per direction a K=16 GEMM
//   D = [logp_i,1] x [p_j,-a_j]^T = -KL(i,j)   (and swapped for KL(j,i))
// folded with predicated adds. No scalar loads, no divergence.
__global__ __launch_bounds__(256, 2) void pair_kernel(
    const float* __restrict__ temperature, float* __restrict__ out) {
    extern __shared__ __align__(1024) unsigned char dsm[];
    __shared__ float s_rk[8];
    __shared__ int   s_rc[8];
    __shared__ double s_fin[6][8];
    __shared__ int s_last;

    int tid  = threadIdx.x;
    int wid  = tid >> 5;
    int lane = tid & 31;

    unsigned dbase = smem_u32(dsm);
    unsigned stA[3], stB[3];
#pragma unroll
    for (int s = 0; s < 3; s++) { stA[s] = dbase + s * SM_STAGE; stB[s] = stA[s] + 8192; }
    unsigned uLi  = dbase + SM_LI,  uPai = dbase + SM_PAI;
    unsigned uLj  = dbase + SM_LJ,  uPaj = dbase + SM_PAJ;

    int mbase = (wid & 3) * 32;
    int nbase = (wid >> 2) * 64;
    int rowA  = ((lane >> 3) & 1) * 8 + (lane & 7);
    int qselA = lane >> 4;
    int rowB  = ((lane >> 4) & 1) * 8 + (lane & 7);
    int qselB = (lane >> 3) & 1;

    // main-GEMM per-lane ldmatrix offsets
    unsigned offA[2][2], offB[4][2];
#pragma unroll
    for (int mt = 0; mt < 2; mt++)
#pragma unroll
        for (int s16 = 0; s16 < 2; s16++)
            offA[mt][s16] = coff(mbase + mt * 16 + rowA, s16 * 2 + qselA);
#pragma unroll
    for (int pnt = 0; pnt < 4; pnt++)
#pragma unroll
        for (int s16 = 0; s16 < 2; s16++)
            offB[pnt][s16] = coff(nbase + pnt * 16 + rowB, s16 * 2 + qselB);

    // K=16 epilogue-GEMM per-lane offsets
    unsigned offA16[2], offB16[4];
#pragma unroll
    for (int mt = 0; mt < 2; mt++)
        offA16[mt] = off16(mbase + mt * 16 + rowA, qselA);
#pragma unroll
    for (int pnt = 0; pnt < 4; pnt++)
        offB16[pnt] = off16(nbase + pnt * 16 + rowB, qselB);

    unsigned co0 = (unsigned)tid * 16u;     // thread's copy slots
    unsigned co1 = co0 + 4096u;

    float kls = 0.f;
    int   cnt = 0;

    // decode first tile
    int ti = 0, rem = blockIdx.x;
    while (rem >= NT - ti) { rem -= NT - ti; ti++; }
    int tj = ti + rem;

    // prologue: chunk0 -> stage0, chunk1 -> stage1
#pragma unroll
    for (int c = 0; c < 2; c++) {
        cpa16(stA[c] + co0, g_ct[c][ti] + co0);
        cpa16(stA[c] + co1, g_ct[c][ti] + co1);
        cpa16(stB[c] + co0, g_ct[c][tj] + co0);
        cpa16(stB[c] + co1, g_ct[c][tj] + co1);
        CP_COMMIT();
    }

    int st = 0;
    for (int t = blockIdx.x; t < NPAIR; t += GRID_PAIR) {
        bool diag = (ti == tj);
        int ti2 = ti, tj2 = tj;
        bool more = (t + GRID_PAIR) < NPAIR;
        if (more) {
            int a = 0, r2 = t + GRID_PAIR;
            while (r2 >= NT - a) { r2 -= NT - a; a++; }
            ti2 = a; tj2 = a + r2;
        }

        float acc[2][8][4];
#pragma unroll
        for (int a = 0; a < 2; a++)
#pragma unroll
            for (int b = 0; b < 8; b++)
#pragma unroll
                for (int c = 0; c < 4; c++) acc[a][b][c] = 0.f;

#pragma unroll
        for (int c = 0; c < 4; c++) {
            CP_WAIT1();
            __syncthreads();
            // issue 2 chunks ahead into stage (st+2)%3
            {
                int tgt = st + 2; if (tgt >= 3) tgt -= 3;
                if (c < 2) {                       // chunks 2,3 of current tile
                    int nc = c + 2;
                    cpa16(stA[tgt] + co0, g_ct[nc][ti] + co0);
                    cpa16(stA[tgt] + co1, g_ct[nc][ti] + co1);
                    cpa16(stB[tgt] + co0, g_ct[nc][tj] + co0);
                    cpa16(stB[tgt] + co1, g_ct[nc][tj] + co1);
                    if (c == 1) {                  // epilogue operand bundle
                        cpa16(uLi  + co0, g_L16 [ti] + co0);
                        cpa16(uPai + co0, g_Pa16[ti] + co0);
                        cpa16(uLj  + co0, g_L16 [tj] + co0);
                        cpa16(uPaj + co0, g_Pa16[tj] + co0);
                    }
                } else if (more) {                 // chunks 0,1 of next tile
                    int nc = c - 2;
                    cpa16(stA[tgt] + co0, g_ct[nc][ti2] + co0);
                    cpa16(stA[tgt] + co1, g_ct[nc][ti2] + co1);
                    cpa16(stB[tgt] + co0, g_ct[nc][tj2] + co0);
                    cpa16(stB[tgt] + co1, g_ct[nc][tj2] + co1);
                }
                CP_COMMIT();                       // always (empty groups at tail)
            }

            // MMA on chunk c from stage st
            unsigned aU = stA[st], bU = stB[st];
#pragma unroll
            for (int s16 = 0; s16 < 2; s16++) {
                unsigned af[2][4], bf[4][4];
#pragma unroll
                for (int mt = 0; mt < 2; mt++) ldsm4(af[mt], aU + offA[mt][s16]);
#pragma unroll
                for (int pnt = 0; pnt < 4; pnt++) ldsm4(bf[pnt], bU + offB[pnt][s16]);
#pragma unroll
                for (int mt = 0; mt < 2; mt++)
#pragma unroll
                    for (int pnt = 0; pnt < 4; pnt++) {
                        mma16816(acc[mt][pnt * 2 + 0], af[mt], &bf[pnt][0]);
                        mma16816(acc[mt][pnt * 2 + 1], af[mt], &bf[pnt][2]);
                    }
            }
            st = st + 1; if (st >= 3) st -= 3;
        }

        // ---- pack threshold masks, free sim accumulators ----
        unsigned msk[2];
#pragma unroll
        for (int mt = 0; mt < 2; mt++) {
            unsigned mw = 0;
#pragma unroll
            for (int nt = 0; nt < 8; nt++)
#pragma unroll
                for (int q = 0; q < 4; q++) {
                    bool pass = acc[mt][nt][q] > 0.8f;
                    if (diag) {
                        int il = mbase + mt * 16 + (q >> 1) * 8 + (lane >> 2);
                        int jl = nbase + nt * 8 + (lane & 3) * 2 + (q & 1);
                        pass = pass && (il != jl);
                    }
                    mw |= (pass ? 1u : 0u) << (nt * 4 + q);
                }
            msk[mt] = mw;
        }
        cnt += (diag ? 1 : 2) * (__popc(msk[0]) + __popc(msk[1]));

        // ---- direction 1: D = L_i x Pa_j^T = -KL(i,j), K=16 GEMM ----
#pragma unroll
        for (int a = 0; a < 2; a++)
#pragma unroll
            for (int b = 0; b < 8; b++)
#pragma unroll
                for (int c = 0; c < 4; c++) acc[a][b][c] = 0.f;
        {
            unsigned af[2][4], bf[4][4];
#pragma unroll
            for (int mt = 0; mt < 2; mt++) ldsm4(af[mt], uLi + offA16[mt]);
#pragma unroll
            for (int pnt = 0; pnt < 4; pnt++) ldsm4(bf[pnt], uPaj + offB16[pnt]);
#pragma unroll
            for (int mt = 0; mt < 2; mt++)
#pragma unroll
                for (int pnt = 0; pnt < 4; pnt++) {
                    mma16816(acc[mt][pnt * 2 + 0], af[mt], &bf[pnt][0]);
                    mma16816(acc[mt][pnt * 2 + 1], af[mt], &bf[pnt][2]);
                }
        }
#pragma unroll
        for (int mt = 0; mt < 2; mt++)
#pragma unroll
            for (int nt = 0; nt < 8; nt++)
#pragma unroll
                for (int q = 0; q < 4; q++)
                    kls -= ((msk[mt] >> (nt * 4 + q)) & 1u) ? acc[mt][nt][q] : 0.f;

        // ---- direction 2 (off-diag): D = Pa_i x L_j^T = -KL(j,i) ----
        if (!diag) {
#pragma unroll
            for (int a = 0; a < 2; a++)
#pragma unroll
                for (int b = 0; b < 8; b++)
#pragma unroll
                    for (int c = 0; c < 4; c++) acc[a][b][c] = 0.f;
            unsigned af[2][4], bf[4][4];
#pragma unroll
            for (int mt = 0; mt < 2; mt++) ldsm4(af[mt], uPai + offA16[mt]);
#pragma unroll
            for (int pnt = 0; pnt < 4; pnt++) ldsm4(bf[pnt], uLj + offB16[pnt]);
#pragma unroll
            for (int mt = 0; mt < 2; mt++)
#pragma unroll
                for (int pnt = 0; pnt < 4; pnt++) {
                    mma16816(acc[mt][pnt * 2 + 0], af[mt], &bf[pnt][0]);
                    mma16816(acc[mt][pnt * 2 + 1], af[mt], &bf[pnt][2]);
                }
#pragma unroll
            for (int mt = 0; mt < 2; mt++)
#pragma unroll
                for (int nt = 0; nt < 8; nt++)
#pragma unroll
                    for (int q = 0; q < 4; q++)
                        kls -= ((msk[mt] >> (nt * 4 + q)) & 1u) ? acc[mt][nt][q] : 0.f;
        }
        ti = ti2; tj = tj2;
    }
    CP_WAIT0();

    // ---- flush per-CTA partial ----
#pragma unroll
    for (int o = 16; o > 0; o >>= 1) {
        kls += __shfl_xor_sync(0xffffffffu, kls, o);
        cnt += __shfl_xor_sync(0xffffffffu, cnt, o);
    }
    if (lane == 0) { s_rk[wid] = kls; s_rc[wid] = cnt; }
    __syncthreads();
    if (tid == 0) {
        double K = 0, C = 0;
        for (int w = 0; w < 8; w++) { K += (double)s_rk[w]; C += (double)s_rc[w]; }
        g_pair_kl[blockIdx.x]  = K;
        g_pair_cnt[blockIdx.x] = C;
        __threadfence();
        unsigned old = atomicAdd(&g_ticket, 1u);
        s_last = ((old % GRID_PAIR) == GRID_PAIR - 1) ? 1 : 0;
    }
    __syncthreads();
    if (!s_last) return;
    __threadfence();

    // ---- last CTA: reduce all partials, compute final loss ----
    double K = 0, C = 0, Tk = 0, Ef = 0, Ent = 0;
    for (int i = tid; i < GRID_PAIR; i += 256) { K += g_pair_kl[i]; C += g_pair_cnt[i]; }
    for (int i = tid; i < PREP_BLKS; i += 256) {
        Tk += g_pp_task[i]; Ef += g_pp_eff[i]; Ent += g_pp_ent[i];
    }
    double Us = 0;                     // warp w reduces expert w
    for (int i = lane; i < PREP_BLKS; i += 32) Us += (double)g_pp_us[i * EN + wid];

    K = wredd(K); C = wredd(C); Tk = wredd(Tk); Ef = wredd(Ef); Ent = wredd(Ent);
    Us = wredd(Us);
    if (lane == 0) {
        s_fin[0][wid] = K;  s_fin[1][wid] = C;  s_fin[2][wid] = Tk;
        s_fin[3][wid] = Ef; s_fin[4][wid] = Ent; s_fin[5][wid] = Us;
    }
    __syncthreads();
    if (tid == 0) {
        double k = 0, c = 0, tk = 0, ef = 0, en = 0;
        for (int w = 0; w < 8; w++) {
            k += s_fin[0][w]; c += s_fin[1][w]; tk += s_fin[2][w];
            ef += s_fin[3][w]; en += s_fin[4][w];
        }
        double u[EN], mu = 0.0;
        for (int e = 0; e < EN; e++) { u[e] = s_fin[5][e] / (double)BN; mu += u[e]; }
        mu /= (double)EN;
        double var = 0.0;
        for (int e = 0; e < EN; e++) var += (u[e] - mu) * (u[e] - mu);
        var /= (double)(EN - 1);
        double cons = (c > 0.0) ? 0.1 * (k / c) : 0.0;
        double tt = (double)temperature[0] - 1.0;
        double loss = tk / (double)BN
                    + 0.1 * var * (double)(EN * EN)
                    + 0.05 * ef / (double)BN
                    + cons
                    + 0.01 * en / (double)BN
                    + 0.01 * tt * tt;
        out[0] = (float)loss;
    }
}

// ---------------- launch -----------------------------------------------------
extern "C" void kernel_launch(void* const* d_in, const int* in_sizes, int n_in,
                              void* d_out, int out_size) {
    const float* logits  = (const float*)d_in[0];
    const int*   targets = (const int*)d_in[1];
    const float* rp      = (const float*)d_in[2];
    const float* emb     = (const float*)d_in[3];
    const float* temp    = (const float*)d_in[4];
    float* out = (float*)d_out;

    static int s_attr_done = 0;
    if (!s_attr_done) {
        cudaFuncSetAttribute(pair_kernel,
                             cudaFuncAttributeMaxDynamicSharedMemorySize, SM_TOTAL);
        s_attr_done = 1;
    }

    prep_kernel<<<PREP_BLKS, 256>>>(logits, targets, rp, emb);
    pair_kernel<<<GRID_PAIR, 256, SM_TOTAL>>>(temp, out);
}

// round 10
// speedup vs baseline: 1.8372x; 1.8372x over previous
#include <cuda_runtime.h>
#include <cuda_bf16.h>

#define BN 8192
#define EN 8
#define HN 128
#define TS 128
#define NT (BN / TS)                 // 64 tiles per dim
#define NPAIR (NT * (NT + 1) / 2)    // 2080 upper-triangular tile pairs
#define GRID_PAIR 296                // 2 CTAs/SM, one wave
#define PREP_BLKS (BN / 8)           // 1024

// dynamic smem layout (bytes)
#define SM_STAGE   16384             // 8KB A + 8KB B per stage
#define SM_STAGES  (3 * SM_STAGE)    // 49152
#define SM_XI      (SM_STAGES)       // X tile, i side (4 KB)
#define SM_YJ      (SM_XI + 4096)    // Y tile, j side (4 KB)
#define SM_TOTAL   (SM_YJ + 4096)    // 57344

// ---------------- device scratch -------------------------------------------
// bf16 main-GEMM tile images in 4 K-chunks of 32:
//   byte(r,q) = (r>>1)*128 + (((r&1)*4) | (q ^ ((r>>1)&3)))*16,  q in 0..3
__device__ __align__(1024) unsigned char g_ct[4][NT][TS * 64];  // 2 MB
// combined KL operand tiles, bf16, 16 cols/row (32 B), layout off16():
//   X_i = [logp_i - a_i (8), p_i (8)] ; Y_j = [p_j (8), logp_j - a_j (8)]
//   X_i . Y_j = -(kl(i,j) + kl(j,i))   (uses sum_e p = 1)
__device__ __align__(1024) unsigned char g_X16[NT][TS * 32];    // 256 KB
__device__ __align__(1024) unsigned char g_Y16[NT][TS * 32];    // 256 KB
// prep per-block partials (written unconditionally -> no zeroing kernel)
__device__ double g_pp_task[PREP_BLKS], g_pp_eff[PREP_BLKS], g_pp_ent[PREP_BLKS];
__device__ float  g_pp_us[PREP_BLKS * EN];
// pair per-CTA partials + never-reset ticket (modular check is replay-safe)
__device__ double g_pair_kl[GRID_PAIR];
__device__ double g_pair_cnt[GRID_PAIR];
__device__ unsigned g_ticket;

// ---------------- PTX helpers ----------------------------------------------
__device__ __forceinline__ unsigned smem_u32(const void* p) {
    unsigned a;
    asm("{ .reg .u64 t; cvta.to.shared.u64 t, %1; cvt.u32.u64 %0, t; }"
        : "=r"(a) : "l"(p));
    return a;
}
__device__ __forceinline__ void ldsm4(unsigned* r, unsigned addr) {
    asm volatile("ldmatrix.sync.aligned.m8n8.x4.shared.b16 {%0,%1,%2,%3}, [%4];"
                 : "=r"(r[0]), "=r"(r[1]), "=r"(r[2]), "=r"(r[3]) : "r"(addr));
}
__device__ __forceinline__ void mma16816(float* d, const unsigned* a, const unsigned* b) {
    asm volatile(
        "mma.sync.aligned.m16n8k16.row.col.f32.bf16.bf16.f32 "
        "{%0,%1,%2,%3}, {%4,%5,%6,%7}, {%8,%9}, {%0,%1,%2,%3};"
        : "+f"(d[0]), "+f"(d[1]), "+f"(d[2]), "+f"(d[3])
        : "r"(a[0]), "r"(a[1]), "r"(a[2]), "r"(a[3]), "r"(b[0]), "r"(b[1]));
}
__device__ __forceinline__ void cpa16(unsigned dst, const void* src) {
    asm volatile("cp.async.cg.shared.global [%0], [%1], 16;"
                 :: "r"(dst), "l"(src) : "memory");
}
#define CP_COMMIT() asm volatile("cp.async.commit_group;" ::: "memory")
#define CP_WAIT1()  asm volatile("cp.async.wait_group 1;" ::: "memory")
#define CP_WAIT0()  asm volatile("cp.async.wait_group 0;" ::: "memory")

// swizzled byte offset within a main-GEMM K-chunk tile
__device__ __forceinline__ unsigned coff(int r, int q) {
    return ((unsigned)(r >> 1) << 7) +
           ((((unsigned)(r & 1) << 2) | ((unsigned)q ^ ((unsigned)(r >> 1) & 3))) << 4);
}
// byte offset within a 128x16 bf16 augmented tile (32 B/row, 4 rows/128B line)
__device__ __forceinline__ unsigned off16(int r, int q) {
    return ((unsigned)(r >> 2) << 7) +
           ((((unsigned)(r & 3) << 1) + ((unsigned)q ^ ((unsigned)(r >> 2) & 1))) << 4);
}
__device__ __forceinline__ unsigned pkbf(float a, float b) {
    return (unsigned)__bfloat16_as_ushort(__float2bfloat16_rn(a)) |
           ((unsigned)__bfloat16_as_ushort(__float2bfloat16_rn(b)) << 16);
}
__device__ __forceinline__ double wredd(double v) {
#pragma unroll
    for (int o = 16; o > 0; o >>= 1) v += __shfl_xor_sync(0xffffffffu, v, o);
    return v;
}

// ---------------- per-row preprocessing + cheap loss partials ---------------
__global__ __launch_bounds__(256) void prep_kernel(
    const float* __restrict__ logits,
    const int* __restrict__ targets,
    const float* __restrict__ rp,
    const float* __restrict__ emb) {
    int warp = threadIdx.x >> 5, lane = threadIdx.x & 31;
    int row = blockIdx.x * 8 + warp;
    __shared__ float  s_us[EN];
    __shared__ double s_task[8], s_eff[8], s_ent[8];
    if (threadIdx.x < EN) s_us[threadIdx.x] = 0.f;
    __syncthreads();

    // normalize embedding row (float4 per lane = 4 consecutive k-cols)
    float4 v = *(const float4*)(emb + (size_t)row * HN + lane * 4);
    float ss = v.x * v.x + v.y * v.y + v.z * v.z + v.w * v.w;
#pragma unroll
    for (int o = 16; o > 0; o >>= 1) ss += __shfl_xor_sync(0xffffffffu, ss, o);
    float inv = rsqrtf(ss);
    float4 w = make_float4(v.x * inv, v.y * inv, v.z * inv, v.w * inv);

    // store bf16 into chunked swizzled main-GEMM tile image
    {
        int cc = lane >> 3;                  // K-chunk 0..3
        int q  = (lane & 7) >> 1;            // 16B chunk in row
        int lr = row & (TS - 1);
        unsigned off = coff(lr, q) + (unsigned)(lane & 1) * 8;
        uint2 val = make_uint2(pkbf(w.x, w.y), pkbf(w.z, w.w));
        *(uint2*)(&g_ct[cc][row >> 7][off]) = val;
    }

    // routing-prob softmax over E=8
    float r = (lane < EN) ? rp[row * EN + lane] : -3.0e38f;
    float m = r;
#pragma unroll
    for (int o = 4; o > 0; o >>= 1) m = fmaxf(m, __shfl_xor_sync(0xffffffffu, m, o));
    float ex = (lane < EN) ? expf(r - m) : 0.f;
    float es = ex;
#pragma unroll
    for (int o = 4; o > 0; o >>= 1) es += __shfl_xor_sync(0xffffffffu, es, o);
    float lse = m + logf(es);
    float lp = r - lse;
    float p  = expf(lp);

    float av  = (lane < EN) ? p * lp : 0.f;
    float evv = (lane < EN && r < 0.1f) ? r : 0.f;
    float nv  = (lane < EN) ? r * logf(r + 1e-8f) : 0.f;
#pragma unroll
    for (int o = 4; o > 0; o >>= 1) {
        av  += __shfl_xor_sync(0xffffffffu, av, o);
        evv += __shfl_xor_sync(0xffffffffu, evv, o);
        nv  += __shfl_xor_sync(0xffffffffu, nv, o);
    }

    // build combined bf16 KL tiles:
    //   X = [logp - a (cols 0-7), p (cols 8-15)]
    //   Y = [p (cols 0-7), logp - a (cols 8-15)]
    {
        float l0 = __shfl_sync(0xffffffffu, lp, (lane & 3) * 2);
        float l1 = __shfl_sync(0xffffffffu, lp, (lane & 3) * 2 + 1);
        float p0 = __shfl_sync(0xffffffffu, p,  (lane & 3) * 2);
        float p1 = __shfl_sync(0xffffffffu, p,  (lane & 3) * 2 + 1);
        if (lane < 8) {
            unsigned lw = pkbf(l0 - av, l1 - av);
            unsigned pw = pkbf(p0, p1);
            unsigned Xw = (lane < 4) ? lw : pw;
            unsigned Yw = (lane < 4) ? pw : lw;
            int lr = row & (TS - 1);
            unsigned off = off16(lr, lane >> 2) + (unsigned)(lane & 3) * 4;
            *(unsigned*)(&g_X16[row >> 7][off]) = Xw;
            *(unsigned*)(&g_Y16[row >> 7][off]) = Yw;
        }
    }

    if (lane < EN) atomicAdd(&s_us[lane], r);
    if (lane == 0) {
        float l0 = logits[row * 3 + 0], l1 = logits[row * 3 + 1], l2 = logits[row * 3 + 2];
        float mm = fmaxf(l0, fmaxf(l1, l2));
        float lsm = mm + logf(expf(l0 - mm) + expf(l1 - mm) + expf(l2 - mm));
        int t = targets[row];
        float lt = (t == 0) ? l0 : ((t == 1) ? l1 : l2);
        s_task[warp] = (double)(lsm - lt);
        s_eff[warp]  = (double)evv;
        s_ent[warp]  = (double)nv;
    }
    __syncthreads();
    if (threadIdx.x == 0) {
        double a = 0, b = 0, c = 0;
        for (int i = 0; i < 8; i++) { a += s_task[i]; b += s_eff[i]; c += s_ent[i]; }
        g_pp_task[blockIdx.x] = a;
        g_pp_eff[blockIdx.x]  = b;
        g_pp_ent[blockIdx.x]  = c;
    }
    if (threadIdx.x < EN) g_pp_us[blockIdx.x * EN + threadIdx.x] = s_us[threadIdx.x];
}

// ---------------- HMMA pair kernel: pipeline + one-GEMM KL epilogue ---------
// Mainloop: 3-stage flat cp.async (unchanged). Epilogue: pack sim masks into
// 2 regs (+popc), then ONE K=16 GEMM  D = X_i x Y_j^T = -(kl(i,j)+kl(j,i)),
// masked-fold, scale 0.5 on diagonal tiles (symmetric mask double-counts).
__global__ __launch_bounds__(256, 2) void pair_kernel(
    const float* __restrict__ temperature, float* __restrict__ out) {
    extern __shared__ __align__(1024) unsigned char dsm[];
    __shared__ float s_rk[8];
    __shared__ int   s_rc[8];
    __shared__ double s_fin[6][8];
    __shared__ int s_last;

    int tid  = threadIdx.x;
    int wid  = tid >> 5;
    int lane = tid & 31;

    unsigned dbase = smem_u32(dsm);
    unsigned stA[3], stB[3];
#pragma unroll
    for (int s = 0; s < 3; s++) { stA[s] = dbase + s * SM_STAGE; stB[s] = stA[s] + 8192; }
    unsigned uXi = dbase + SM_XI, uYj = dbase + SM_YJ;

    int mbase = (wid & 3) * 32;
    int nbase = (wid >> 2) * 64;
    int rowA  = ((lane >> 3) & 1) * 8 + (lane & 7);
    int qselA = lane >> 4;
    int rowB  = ((lane >> 4) & 1) * 8 + (lane & 7);
    int qselB = (lane >> 3) & 1;

    // main-GEMM per-lane ldmatrix offsets
    unsigned offA[2][2], offB[4][2];
#pragma unroll
    for (int mt = 0; mt < 2; mt++)
#pragma unroll
        for (int s16 = 0; s16 < 2; s16++)
            offA[mt][s16] = coff(mbase + mt * 16 + rowA, s16 * 2 + qselA);
#pragma unroll
    for (int pnt = 0; pnt < 4; pnt++)
#pragma unroll
        for (int s16 = 0; s16 < 2; s16++)
            offB[pnt][s16] = coff(nbase + pnt * 16 + rowB, s16 * 2 + qselB);

    // K=16 epilogue-GEMM per-lane offsets
    unsigned offA16[2], offB16[4];
#pragma unroll
    for (int mt = 0; mt < 2; mt++)
        offA16[mt] = off16(mbase + mt * 16 + rowA, qselA);
#pragma unroll
    for (int pnt = 0; pnt < 4; pnt++)
        offB16[pnt] = off16(nbase + pnt * 16 + rowB, qselB);

    unsigned co0 = (unsigned)tid * 16u;     // thread's copy slots
    unsigned co1 = co0 + 4096u;

    float kls = 0.f;
    int   cnt = 0;

    // decode first tile
    int ti = 0, rem = blockIdx.x;
    while (rem >= NT - ti) { rem -= NT - ti; ti++; }
    int tj = ti + rem;

    // prologue: chunk0 -> stage0, chunk1 -> stage1
#pragma unroll
    for (int c = 0; c < 2; c++) {
        cpa16(stA[c] + co0, g_ct[c][ti] + co0);
        cpa16(stA[c] + co1, g_ct[c][ti] + co1);
        cpa16(stB[c] + co0, g_ct[c][tj] + co0);
        cpa16(stB[c] + co1, g_ct[c][tj] + co1);
        CP_COMMIT();
    }

    int st = 0;
    for (int t = blockIdx.x; t < NPAIR; t += GRID_PAIR) {
        bool diag = (ti == tj);
        int ti2 = ti, tj2 = tj;
        bool more = (t + GRID_PAIR) < NPAIR;
        if (more) {
            int a = 0, r2 = t + GRID_PAIR;
            while (r2 >= NT - a) { r2 -= NT - a; a++; }
            ti2 = a; tj2 = a + r2;
        }

        float acc[2][8][4];
#pragma unroll
        for (int a = 0; a < 2; a++)
#pragma unroll
            for (int b = 0; b < 8; b++)
#pragma unroll
                for (int c = 0; c < 4; c++) acc[a][b][c] = 0.f;

#pragma unroll
        for (int c = 0; c < 4; c++) {
            CP_WAIT1();
            __syncthreads();
            // issue 2 chunks ahead into stage (st+2)%3
            {
                int tgt = st + 2; if (tgt >= 3) tgt -= 3;
                if (c < 2) {                       // chunks 2,3 of current tile
                    int nc = c + 2;
                    cpa16(stA[tgt] + co0, g_ct[nc][ti] + co0);
                    cpa16(stA[tgt] + co1, g_ct[nc][ti] + co1);
                    cpa16(stB[tgt] + co0, g_ct[nc][tj] + co0);
                    cpa16(stB[tgt] + co1, g_ct[nc][tj] + co1);
                    if (c == 1) {                  // epilogue operand bundle
                        cpa16(uXi + co0, g_X16[ti] + co0);
                        cpa16(uYj + co0, g_Y16[tj] + co0);
                    }
                } else if (more) {                 // chunks 0,1 of next tile
                    int nc = c - 2;
                    cpa16(stA[tgt] + co0, g_ct[nc][ti2] + co0);
                    cpa16(stA[tgt] + co1, g_ct[nc][ti2] + co1);
                    cpa16(stB[tgt] + co0, g_ct[nc][tj2] + co0);
                    cpa16(stB[tgt] + co1, g_ct[nc][tj2] + co1);
                }
                CP_COMMIT();                       // always (empty groups at tail)
            }

            // MMA on chunk c from stage st
            unsigned aU = stA[st], bU = stB[st];
#pragma unroll
            for (int s16 = 0; s16 < 2; s16++) {
                unsigned af[2][4], bf[4][4];
#pragma unroll
                for (int mt = 0; mt < 2; mt++) ldsm4(af[mt], aU + offA[mt][s16]);
#pragma unroll
                for (int pnt = 0; pnt < 4; pnt++) ldsm4(bf[pnt], bU + offB[pnt][s16]);
#pragma unroll
                for (int mt = 0; mt < 2; mt++)
#pragma unroll
                    for (int pnt = 0; pnt < 4; pnt++) {
                        mma16816(acc[mt][pnt * 2 + 0], af[mt], &bf[pnt][0]);
                        mma16816(acc[mt][pnt * 2 + 1], af[mt], &bf[pnt][2]);
                    }
            }
            st = st + 1; if (st >= 3) st -= 3;
        }

        // ---- pack threshold masks (diag branch hoisted) ----
        unsigned msk[2];
        if (!diag) {
#pragma unroll
            for (int mt = 0; mt < 2; mt++) {
                unsigned mw = 0;
#pragma unroll
                for (int nt = 0; nt < 8; nt++)
#pragma unroll
                    for (int q = 0; q < 4; q++)
                        mw |= (acc[mt][nt][q] > 0.8f ? 1u : 0u) << (nt * 4 + q);
                msk[mt] = mw;
            }
            cnt += 2 * (__popc(msk[0]) + __popc(msk[1]));
        } else {
#pragma unroll
            for (int mt = 0; mt < 2; mt++) {
                unsigned mw = 0;
#pragma unroll
                for (int nt = 0; nt < 8; nt++)
#pragma unroll
                    for (int q = 0; q < 4; q++) {
                        int il = mbase + mt * 16 + (q >> 1) * 8 + (lane >> 2);
                        int jl = nbase + nt * 8 + (lane & 3) * 2 + (q & 1);
                        bool pass = (acc[mt][nt][q] > 0.8f) && (il != jl);
                        mw |= (pass ? 1u : 0u) << (nt * 4 + q);
                    }
                msk[mt] = mw;
            }
            cnt += __popc(msk[0]) + __popc(msk[1]);
        }

        // ---- ONE K=16 GEMM: D = X_i x Y_j^T = -(kl(i,j)+kl(j,i)) ----
#pragma unroll
        for (int a = 0; a < 2; a++)
#pragma unroll
            for (int b = 0; b < 8; b++)
#pragma unroll
                for (int c = 0; c < 4; c++) acc[a][b][c] = 0.f;
        {
            unsigned af[2][4], bf[4][4];
#pragma unroll
            for (int mt = 0; mt < 2; mt++) ldsm4(af[mt], uXi + offA16[mt]);
#pragma unroll
            for (int pnt = 0; pnt < 4; pnt++) ldsm4(bf[pnt], uYj + offB16[pnt]);
#pragma unroll
            for (int mt = 0; mt < 2; mt++)
#pragma unroll
                for (int pnt = 0; pnt < 4; pnt++) {
                    mma16816(acc[mt][pnt * 2 + 0], af[mt], &bf[pnt][0]);
                    mma16816(acc[mt][pnt * 2 + 1], af[mt], &bf[pnt][2]);
                }
        }
        float S = 0.f;
#pragma unroll
        for (int mt = 0; mt < 2; mt++)
#pragma unroll
            for (int nt = 0; nt < 8; nt++)
#pragma unroll
                for (int q = 0; q < 4; q++)
                    S += ((msk[mt] >> (nt * 4 + q)) & 1u) ? acc[mt][nt][q] : 0.f;
        kls -= diag ? 0.5f * S : S;    // D = -(kl sum); diag double-counts pairs

        ti = ti2; tj = tj2;
    }
    CP_WAIT0();

    // ---- flush per-CTA partial ----
#pragma unroll
    for (int o = 16; o > 0; o >>= 1) {
        kls += __shfl_xor_sync(0xffffffffu, kls, o);
        cnt += __shfl_xor_sync(0xffffffffu, cnt, o);
    }
    if (lane == 0) { s_rk[wid] = kls; s_rc[wid] = cnt; }
    __syncthreads();
    if (tid == 0) {
        double K = 0, C = 0;
        for (int w = 0; w < 8; w++) { K += (double)s_rk[w]; C += (double)s_rc[w]; }
        g_pair_kl[blockIdx.x]  = K;
        g_pair_cnt[blockIdx.x] = C;
        __threadfence();
        unsigned old = atomicAdd(&g_ticket, 1u);
        s_last = ((old % GRID_PAIR) == GRID_PAIR - 1) ? 1 : 0;
    }
    __syncthreads();
    if (!s_last) return;
    __threadfence();

    // ---- last CTA: reduce all partials, compute final loss ----
    double K = 0, C = 0, Tk = 0, Ef = 0, Ent = 0;
    for (int i = tid; i < GRID_PAIR; i += 256) { K += g_pair_kl[i]; C += g_pair_cnt[i]; }
    for (int i = tid; i < PREP_BLKS; i += 256) {
        Tk += g_pp_task[i]; Ef += g_pp_eff[i]; Ent += g_pp_ent[i];
    }
    double Us = 0;                     // warp w reduces expert w
    for (int i = lane; i < PREP_BLKS; i += 32) Us += (double)g_pp_us[i * EN + wid];

    K = wredd(K); C = wredd(C); Tk = wredd(Tk); Ef = wredd(Ef); Ent = wredd(Ent);
    Us = wredd(Us);
    if (lane == 0) {
        s_fin[0][wid] = K;  s_fin[1][wid] = C;  s_fin[2][wid] = Tk;
        s_fin[3][wid] = Ef; s_fin[4][wid] = Ent; s_fin[5][wid] = Us;
    }
    __syncthreads();
    if (tid == 0) {
        double k = 0, c = 0, tk = 0, ef = 0, en = 0;
        for (int w = 0; w < 8; w++) {
            k += s_fin[0][w]; c += s_fin[1][w]; tk += s_fin[2][w];
            ef += s_fin[3][w]; en += s_fin[4][w];
        }
        double u[EN], mu = 0.0;
        for (int e = 0; e < EN; e++) { u[e] = s_fin[5][e] / (double)BN; mu += u[e]; }
        mu /= (double)EN;
        double var = 0.0;
        for (int e = 0; e < EN; e++) var += (u[e] - mu) * (u[e] - mu);
        var /= (double)(EN - 1);
        double cons = (c > 0.0) ? 0.1 * (k / c) : 0.0;
        double tt = (double)temperature[0] - 1.0;
        double loss = tk / (double)BN
                    + 0.1 * var * (double)(EN * EN)
                    + 0.05 * ef / (double)BN
                    + cons
                    + 0.01 * en / (double)BN
                    + 0.01 * tt * tt;
        out[0] = (float)loss;
    }
}

// ---------------- launch -----------------------------------------------------
extern "C" void kernel_launch(void* const* d_in, const int* in_sizes, int n_in,
                              void* d_out, int out_size) {
    const float* logits  = (const float*)d_in[0];
    const int*   targets = (const int*)d_in[1];
    const float* rp      = (const float*)d_in[2];
    const float* emb     = (const float*)d_in[3];
    const float* temp    = (const float*)d_in[4];
    float* out = (float*)d_out;

    static int s_attr_done = 0;
    if (!s_attr_done) {
        cudaFuncSetAttribute(pair_kernel,
                             cudaFuncAttributeMaxDynamicSharedMemorySize, SM_TOTAL);
        s_attr_done = 1;
    }

    prep_kernel<<<PREP_BLKS, 256>>>(logits, targets, rp, emb);
    pair_kernel<<<GRID_PAIR, 256, SM_TOTAL>>>(temp, out);
}